// round 16
// baseline (speedup 1.0000x reference)
#include <cuda_runtime.h>
#include <cuda_bf16.h>
#include <math.h>
#include <stdint.h>

// Problem constants
#define NN    8192
#define HH    512
#define DD    256
#define GG    64
#define M2    16384
#define EPS_G 1e-6f
#define EPS_L 1e-5f

// ---------------- scratch (static device allocations; no cudaMalloc) ----------------
__device__ __nv_bfloat16 g_x0h[M2 * HH], g_x0l[M2 * HH];  // layer1 input (za|zb split)
__device__ __nv_bfloat16 g_x1h[M2 * HH], g_x1l[M2 * HH];  // layer1 out / layer2 in
__device__ __nv_bfloat16 g_x2h[M2 * HH], g_x2l[M2 * HH];  // layer2 out / layer3 in
__device__ __nv_bfloat16 g_w1h[HH * HH], g_w1l[HH * HH];  // W1^T hi/lo  [N,K]
__device__ __nv_bfloat16 g_w2h[HH * HH], g_w2l[HH * HH];  // W2^T
__device__ __nv_bfloat16 g_w3h[DD * HH], g_w3l[DD * HH];  // W3^T  [256,512]
__device__ float g_proj[NN * (2 * DD)];                   // fp32 projections (interleaved)
__device__ __nv_bfloat16 g_Ahi[NN * DD];                  // normalized * 2/tau (bf16)
__device__ __nv_bfloat16 g_Bhi[NN * DD];                  // normalized (bf16)
__device__ float g_rowsum[NN];
__device__ float g_colsum[NN];
__device__ float g_rowdot[NN];
__device__ float g_coldot[NN];
__device__ float g_bsim[GG * GG];
__device__ float g_psg[GG];

// ---------------- portable tensor-core helpers (sm_80+ baseline ISA) ----------------
__device__ __forceinline__ uint32_t smem_u32(const void* p) {
    uint32_t a;
    asm("{ .reg .u64 t; cvta.to.shared.u64 t, %1; cvt.u32.u64 %0, t; }" : "=r"(a) : "l"(p));
    return a;
}
__device__ __forceinline__ void ldm_x4(uint32_t* r, uint32_t a) {
    asm volatile("ldmatrix.sync.aligned.m8n8.x4.shared.b16 {%0,%1,%2,%3}, [%4];"
                 : "=r"(r[0]), "=r"(r[1]), "=r"(r[2]), "=r"(r[3]) : "r"(a));
}
__device__ __forceinline__ void ldm_x2(uint32_t* r, uint32_t a) {
    asm volatile("ldmatrix.sync.aligned.m8n8.x2.shared.b16 {%0,%1}, [%2];"
                 : "=r"(r[0]), "=r"(r[1]) : "r"(a));
}
__device__ __forceinline__ void mma_bf16(float* c, const uint32_t* a, const uint32_t* b) {
    asm volatile("mma.sync.aligned.m16n8k16.row.col.f32.bf16.bf16.f32 "
                 "{%0,%1,%2,%3}, {%4,%5,%6,%7}, {%8,%9}, {%0,%1,%2,%3};"
                 : "+f"(c[0]), "+f"(c[1]), "+f"(c[2]), "+f"(c[3])
                 : "r"(a[0]), "r"(a[1]), "r"(a[2]), "r"(a[3]), "r"(b[0]), "r"(b[1]));
}
__device__ __forceinline__ void split_bf16(float v, __nv_bfloat16& hi, __nv_bfloat16& lo) {
    hi = __float2bfloat16(v);
    lo = __float2bfloat16(v - __bfloat162float(hi));
}
__device__ __forceinline__ void cp_async16(uint32_t saddr, const void* gptr) {
    asm volatile("cp.async.cg.shared.global [%0], [%1], 16;"
                 :: "r"(saddr), "l"(gptr) : "memory");
}
__device__ __forceinline__ void cp_commit() {
    asm volatile("cp.async.commit_group;" ::: "memory");
}
__device__ __forceinline__ void cp_wait0() {
    asm volatile("cp.async.wait_group 0;" ::: "memory");
}
__device__ __forceinline__ void cp_wait1() {
    asm volatile("cp.async.wait_group 1;" ::: "memory");
}

// ---------------- fused prep: input split + weight transpose/split + zeroing --------
__global__ void prep_kernel(const float* __restrict__ za, const float* __restrict__ zb,
                            const float* __restrict__ W1, const float* __restrict__ W2,
                            const float* __restrict__ W3) {
    int t = blockIdx.x * blockDim.x + threadIdx.x;
    if (t < NN * HH) {
        __nv_bfloat16 hi, lo;
        split_bf16(za[t], hi, lo);
        g_x0h[t] = hi; g_x0l[t] = lo;
        split_bf16(zb[t], hi, lo);
        g_x0h[t + NN * HH] = hi; g_x0l[t + NN * HH] = lo;
    }
    if (t < NN) {
        g_rowsum[t] = 0.f; g_colsum[t] = 0.f;
        g_rowdot[t] = 0.f; g_coldot[t] = 0.f;
    }
    if (t < 2 * HH * HH + DD * HH) {
        const float* W; __nv_bfloat16 *Th, *Tl; int Nw, e;
        if (t < HH * HH)            { W = W1; Th = g_w1h; Tl = g_w1l; Nw = HH; e = t; }
        else if (t < 2 * HH * HH)   { W = W2; Th = g_w2h; Tl = g_w2l; Nw = HH; e = t - HH * HH; }
        else                        { W = W3; Th = g_w3h; Tl = g_w3l; Nw = DD; e = t - 2 * HH * HH; }
        int n = e >> 9, k = e & 511;
        float v = W[(size_t)k * Nw + n];
        __nv_bfloat16 hi, lo; split_bf16(v, hi, lo);
        Th[e] = hi; Tl[e] = lo;
    }
}

// ---------------- bf16x3 MLP GEMM (3-term waves, independent-chain ordering) ---------
#define SM_A_HI 0
#define SM_A_LO 16384
#define SM_B_HI 32768
#define SM_B_LO 49152
#define MLP_SMEM_TOTAL 65536

__global__ __launch_bounds__(256, 2) void mlp_mma(
    const __nv_bfloat16* __restrict__ Ah, const __nv_bfloat16* __restrict__ Al,
    const __nv_bfloat16* __restrict__ Bh, const __nv_bfloat16* __restrict__ Bl,
    int K,
    const float* __restrict__ bias,
    const float* __restrict__ aP, const float* __restrict__ gP, const float* __restrict__ beP,
    __nv_bfloat16* __restrict__ Oh, __nv_bfloat16* __restrict__ Ol,
    float* __restrict__ Cp, float* __restrict__ C2,
    int mode)
{
    extern __shared__ char smem[];
    uint32_t sb = smem_u32(smem);
    int tid = threadIdx.x;
    int w = tid >> 5, lane = tid & 31;
    int wm = w >> 2, wn = w & 3;          // 2x4 warp grid, 64x32 warp tile
    int i0 = blockIdx.y * 128, j0 = blockIdx.x * 128;

    float c[4][4][4];
#pragma unroll
    for (int mi = 0; mi < 4; mi++)
#pragma unroll
        for (int ni = 0; ni < 4; ni++)
#pragma unroll
            for (int q = 0; q < 4; q++) c[mi][ni][q] = 0.f;

    int srow = tid >> 1, sseg = tid & 1;
    size_t aidx0 = (size_t)(i0 + srow) * K + sseg * 32;
    size_t bidx0 = (size_t)(j0 + srow) * K + sseg * 32;

    int rA = lane & 15;
    int cbA = (lane >> 4) * 16;
    int rB = lane & 7;
    int cbB = ((lane >> 3) & 1) * 16;

    int nkc = K >> 6;
    for (int kc = 0; kc < nkc; kc++) {
        size_t aidx = aidx0 + kc * 64;
        size_t bidx = bidx0 + kc * 64;
#pragma unroll
        for (int q = 0; q < 4; q++) {
            uint32_t off = (uint32_t)(srow * 128 + sseg * 64 + q * 16);
            uint32_t sw = off ^ ((off >> 3) & 0x70);
            *(uint4*)(smem + SM_A_HI + sw) = *(const uint4*)(Ah + aidx + q * 8);
            *(uint4*)(smem + SM_A_LO + sw) = *(const uint4*)(Al + aidx + q * 8);
            *(uint4*)(smem + SM_B_HI + sw) = *(const uint4*)(Bh + bidx + q * 8);
            *(uint4*)(smem + SM_B_LO + sw) = *(const uint4*)(Bl + bidx + q * 8);
        }
        __syncthreads();

#pragma unroll
        for (int ks = 0; ks < 4; ks++) {
            // load ALL fragments first (grouped LDSM)
            uint32_t bhi[4][2], blo[4][2];
#pragma unroll
            for (int ni = 0; ni < 4; ni++) {
                uint32_t off = (uint32_t)((wn * 32 + ni * 8 + rB) * 128 + ks * 32 + cbB);
                uint32_t sw = off ^ ((off >> 3) & 0x70);
                ldm_x2(bhi[ni], sb + SM_B_HI + sw);
                ldm_x2(blo[ni], sb + SM_B_LO + sw);
            }
            uint32_t ahi[4][4], alo[4][4];
#pragma unroll
            for (int mi = 0; mi < 4; mi++) {
                uint32_t off = (uint32_t)((wm * 64 + mi * 16 + rA) * 128 + ks * 32 + cbA);
                uint32_t sw = off ^ ((off >> 3) & 0x70);
                ldm_x4(ahi[mi], sb + SM_A_HI + sw);
                ldm_x4(alo[mi], sb + SM_A_LO + sw);
            }
            // wave 1: hi*hi (16 independent)
#pragma unroll
            for (int mi = 0; mi < 4; mi++)
#pragma unroll
                for (int ni = 0; ni < 4; ni++)
                    mma_bf16(c[mi][ni], ahi[mi], bhi[ni]);
            // wave 2: hi*lo (16 independent)
#pragma unroll
            for (int mi = 0; mi < 4; mi++)
#pragma unroll
                for (int ni = 0; ni < 4; ni++)
                    mma_bf16(c[mi][ni], ahi[mi], blo[ni]);
            // wave 3: lo*hi (16 independent)
#pragma unroll
            for (int mi = 0; mi < 4; mi++)
#pragma unroll
                for (int ni = 0; ni < 4; ni++)
                    mma_bf16(c[mi][ni], alo[mi], bhi[ni]);
        }
        __syncthreads();
    }

    // ---- epilogue ----
    if (mode == 0) {
        float a0 = aP[0];
#pragma unroll
        for (int mi = 0; mi < 4; mi++) {
#pragma unroll
            for (int h = 0; h < 2; h++) {
                int m = i0 + wm * 64 + mi * 16 + h * 8 + (lane >> 2);
#pragma unroll
                for (int ni = 0; ni < 4; ni++) {
                    int c0 = j0 + wn * 32 + ni * 8 + (lane & 3) * 2;
                    float v0 = tanhf(a0 * (c[mi][ni][2 * h + 0] + bias[c0])) * gP[c0] + beP[c0];
                    float v1 = tanhf(a0 * (c[mi][ni][2 * h + 1] + bias[c0 + 1])) * gP[c0 + 1] + beP[c0 + 1];
                    __nv_bfloat16 h0, l0, h1, l1;
                    split_bf16(v0, h0, l0);
                    split_bf16(v1, h1, l1);
                    size_t idx = (size_t)m * 512 + c0;
                    *(__nv_bfloat162*)(Oh + idx) = __nv_bfloat162(h0, h1);
                    *(__nv_bfloat162*)(Ol + idx) = __nv_bfloat162(l0, l1);
                }
            }
        }
    } else {
#pragma unroll
        for (int mi = 0; mi < 4; mi++) {
#pragma unroll
            for (int h = 0; h < 2; h++) {
                int m = i0 + wm * 64 + mi * 16 + h * 8 + (lane >> 2);
                size_t base = (m < NN) ? ((size_t)m * 512) : ((size_t)(m - NN) * 512 + 256);
#pragma unroll
                for (int ni = 0; ni < 4; ni++) {
                    int c0 = j0 + wn * 32 + ni * 8 + (lane & 3) * 2;
                    float v0 = c[mi][ni][2 * h + 0] + bias[c0];
                    float v1 = c[mi][ni][2 * h + 1] + bias[c0 + 1];
                    v0 = v0 / (1.f + expf(-v0));
                    v1 = v1 / (1.f + expf(-v1));
                    size_t pr = base + c0;
                    Cp[pr] = v0; Cp[pr + 1] = v1;
                    C2[pr] = v0; C2[pr + 1] = v1;
                }
            }
        }
    }
}

// ---------------- per-row norm + bf16 quantize (2/tau folded into A) ----------------
__global__ void norm_split_kernel() {
    int warp = (blockIdx.x * blockDim.x + threadIdx.x) >> 5;
    int lane = threadIdx.x & 31;
    if (warp >= NN) return;
    const float* pa = g_proj + (size_t)warp * 512;
    float sa = 0.f, sb = 0.f;
#pragma unroll
    for (int k = lane; k < 256; k += 32) {
        float v = pa[k];        sa += v * v;
        float w = pa[256 + k];  sb += w * w;
    }
#pragma unroll
    for (int o = 16; o; o >>= 1) {
        sa += __shfl_xor_sync(0xffffffffu, sa, o);
        sb += __shfl_xor_sync(0xffffffffu, sb, o);
    }
    float ia = 2.0f * rsqrtf(sa);
    float ib = rsqrtf(sb);
#pragma unroll
    for (int k = lane; k < 256; k += 32) {
        g_Ahi[(size_t)warp * 256 + k] = __float2bfloat16(pa[k] * ia);
        g_Bhi[(size_t)warp * 256 + k] = __float2bfloat16(pa[256 + k] * ib);
    }
}

// ---------------- paired-tile 1-term bf16 sim + fused reductions ---------------------
#define SIMD_A0 0
#define SIMD_B0 16384
#define SIMD_A1 32768
#define SIMD_B1 49152
#define SM_RS   66048
#define SM_RD   66560
#define SM_CS   67072
#define SM_CD   67584
#define SM_TS   68096
#define SM_PSG  68100
#define SIM_SMEM_TOTAL 68352

__global__ __launch_bounds__(256, 2) void sim_pair(const float* __restrict__ pos) {
    int by = blockIdx.y, bx = blockIdx.x;
    if (by > bx) return;                  // upper-triangle CTAs only
    extern __shared__ char smem[];
    uint32_t sb = smem_u32(smem);
    int tid = threadIdx.x;
    int w = tid >> 5, lane = tid & 31;
    int wm = w >> 2, wn = w & 3;

    float* s_rs = (float*)(smem + SM_RS);
    float* s_rd = (float*)(smem + SM_RD);
    float* s_cs = (float*)(smem + SM_CS);
    float* s_cd = (float*)(smem + SM_CD);
    float* smf  = (float*)smem;

    int srow = tid >> 1, sseg = tid & 1;
    int rA = lane & 15;
    int cbA = (lane >> 4) * 16;
    int rB = lane & 7;
    int cbB = ((lane >> 3) & 1) * 16;
    uint32_t soff0 = (uint32_t)(srow * 128 + sseg * 64);

    int npass = (by == bx) ? 1 : 2;
    for (int pass = 0; pass < npass; pass++) {
        int I = pass ? bx : by;
        int J = pass ? by : bx;
        int i0 = I * 128, j0 = J * 128;

        if (tid == 0) { *(float*)(smem + SM_TS) = 0.f; *(float*)(smem + SM_PSG) = 0.f; }
        if (tid < 128) { s_rs[tid] = 0.f; s_rd[tid] = 0.f; }

        float c[4][4][4];
#pragma unroll
        for (int mi = 0; mi < 4; mi++)
#pragma unroll
            for (int ni = 0; ni < 4; ni++)
#pragma unroll
                for (int q = 0; q < 4; q++) c[mi][ni][q] = 0.f;

        size_t aidx0 = (size_t)(i0 + srow) * 256 + sseg * 32;
        size_t bidx0 = (size_t)(j0 + srow) * 256 + sseg * 32;

        // prologue: stage chunk 0 into buf0
#pragma unroll
        for (int q = 0; q < 4; q++) {
            uint32_t off = soff0 + q * 16;
            uint32_t sw = off ^ ((off >> 3) & 0x70);
            cp_async16(sb + SIMD_A0 + sw, g_Ahi + aidx0 + q * 8);
            cp_async16(sb + SIMD_B0 + sw, g_Bhi + bidx0 + q * 8);
        }
        cp_commit();

        for (int kc = 0; kc < 4; kc++) {
            if (kc < 3) {
                uint32_t abase = (kc & 1) ? SIMD_A0 : SIMD_A1;   // next buffer
                uint32_t bbase = (kc & 1) ? SIMD_B0 : SIMD_B1;
                size_t aidx = aidx0 + (kc + 1) * 64;
                size_t bidx = bidx0 + (kc + 1) * 64;
#pragma unroll
                for (int q = 0; q < 4; q++) {
                    uint32_t off = soff0 + q * 16;
                    uint32_t sw = off ^ ((off >> 3) & 0x70);
                    cp_async16(sb + abase + sw, g_Ahi + aidx + q * 8);
                    cp_async16(sb + bbase + sw, g_Bhi + bidx + q * 8);
                }
                cp_commit();
                cp_wait1();
            } else {
                cp_wait0();
            }
            __syncthreads();

            uint32_t aC = (kc & 1) ? SIMD_A1 : SIMD_A0;          // current buffer
            uint32_t bC = (kc & 1) ? SIMD_B1 : SIMD_B0;
#pragma unroll
            for (int ks = 0; ks < 4; ks++) {
                uint32_t bf[4][2];
#pragma unroll
                for (int ni = 0; ni < 4; ni++) {
                    uint32_t off = (uint32_t)((wn * 32 + ni * 8 + rB) * 128 + ks * 32 + cbB);
                    uint32_t sw = off ^ ((off >> 3) & 0x70);
                    ldm_x2(bf[ni], sb + bC + sw);
                }
#pragma unroll
                for (int mi = 0; mi < 4; mi++) {
                    uint32_t af[4];
                    uint32_t off = (uint32_t)((wm * 64 + mi * 16 + rA) * 128 + ks * 32 + cbA);
                    uint32_t sw = off ^ ((off >> 3) & 0x70);
                    ldm_x4(af, sb + aC + sw);
#pragma unroll
                    for (int ni = 0; ni < 4; ni++)
                        mma_bf16(c[mi][ni], af, bf[ni]);
                }
            }
            __syncthreads();
        }

        // ---- epilogue: exp, row reductions + pos row-pass, stage m-tile ----
        float tsl = 0.f;
#pragma unroll
        for (int mi = 0; mi < 4; mi++) {
#pragma unroll
            for (int h = 0; h < 2; h++) {
                int row_local = wm * 64 + mi * 16 + h * 8 + (lane >> 2);
                int gi = i0 + row_local;
                float rsum = 0.f, rdot = 0.f;
#pragma unroll
                for (int ni = 0; ni < 4; ni++) {
                    int col_local = wn * 32 + ni * 8 + (lane & 3) * 2;
                    float e0 = expf(c[mi][ni][2 * h + 0]);
                    float e1 = expf(c[mi][ni][2 * h + 1]);
                    smf[(size_t)row_local * 129 + col_local]     = e0;
                    smf[(size_t)row_local * 129 + col_local + 1] = e1;
                    const float2 p = *(const float2*)(pos + (size_t)gi * NN + j0 + col_local);
                    rsum += e0 + e1;
                    rdot += e0 * p.x + e1 * p.y;
                }
                atomicAdd(&s_rs[row_local], rsum);
                atomicAdd(&s_rd[row_local], rdot);
                tsl += rsum;
            }
        }
#pragma unroll
        for (int o = 16; o; o >>= 1) tsl += __shfl_xor_sync(0xffffffffu, tsl, o);
        if (lane == 0) atomicAdd((float*)(smem + SM_TS), tsl);
        __syncthreads();   // m-tile complete

        // column reductions: warp w owns pos-rows [w*16, w*16+16); per row the
        // 32 lanes read one contiguous float4 each (coalesced 512B), then
        // shuffle-reduce; lane 0 direct-stores (unique writer per cc).
        {
            int cc0 = w * 16;
            for (int r = 0; r < 16; r++) {
                int cc = cc0 + r;
                const float4 p = *(const float4*)(pos + (size_t)(j0 + cc) * NN + i0 + lane * 4);
                float m0 = smf[(size_t)(lane * 4 + 0) * 129 + cc];
                float m1 = smf[(size_t)(lane * 4 + 1) * 129 + cc];
                float m2 = smf[(size_t)(lane * 4 + 2) * 129 + cc];
                float m3 = smf[(size_t)(lane * 4 + 3) * 129 + cc];
                float cs = m0 + m1 + m2 + m3;
                float cd = m0 * p.x + m1 * p.y + m2 * p.z + m3 * p.w;
#pragma unroll
                for (int o = 16; o; o >>= 1) {
                    cs += __shfl_xor_sync(0xffffffffu, cs, o);
                    cd += __shfl_xor_sync(0xffffffffu, cd, o);
                }
                if (lane == 0) { s_cs[cc] = cs; s_cd[cc] = cd; }
            }
        }
        if (i0 == j0 && tid < 128)
            atomicAdd((float*)(smem + SM_PSG), smf[(size_t)tid * 129 + tid]);
        __syncthreads();

        if (tid < 128) {
            atomicAdd(&g_rowsum[i0 + tid], s_rs[tid]);
            atomicAdd(&g_rowdot[i0 + tid], s_rd[tid]);
            atomicAdd(&g_colsum[j0 + tid], s_cs[tid]);
            atomicAdd(&g_coldot[j0 + tid], s_cd[tid]);
        }
        if (tid == 0) {
            g_bsim[I * GG + J] = *(float*)(smem + SM_TS);   // unique (I,J) per pass
            if (I == J) g_psg[I] = *(float*)(smem + SM_PSG);
        }
        __syncthreads();   // protect smem before next pass restages
    }
}

// ---------------- final scalar loss ----------------
__global__ void finalize_kernel(float* __restrict__ out) {
    __shared__ float red[512];
    int t = threadIdx.x;

    float la = 0.f, lb = 0.f;
    for (int i = t; i < NN; i += 512) {
        la += logf(g_rowdot[i] / (g_rowsum[i] + EPS_G));
        lb += logf(g_coldot[i] / (g_colsum[i] + EPS_G));
    }
    red[t] = la; __syncthreads();
    for (int s = 256; s >= 1; s >>= 1) { if (t < s) red[t] += red[t + s]; __syncthreads(); }
    float suma = red[0]; __syncthreads();
    red[t] = lb; __syncthreads();
    for (int s = 256; s >= 1; s >>= 1) { if (t < s) red[t] += red[t + s]; __syncthreads(); }
    float sumb = red[0]; __syncthreads();

    float t0 = 0.f, t1 = 0.f, tin = 0.f;
    if (t < GG) {
        float graph = g_bsim[t * GG + t];
        float n0 = 0.f, n1 = 0.f;
        for (int a = 0; a < GG; a++) { n0 += g_bsim[a * GG + t]; n1 += g_bsim[t * GG + a]; }
        n0 -= graph; n1 -= graph;
        float psg = g_psg[t];
        t0  = logf(psg / (n0 + EPS_L));
        t1  = logf(psg / (n1 + EPS_L));
        tin = logf(psg / (graph - psg + EPS_L));
    }
    red[t] = t0; __syncthreads();
    for (int s = 256; s >= 1; s >>= 1) { if (t < s) red[t] += red[t + s]; __syncthreads(); }
    float s0 = red[0]; __syncthreads();
    red[t] = t1; __syncthreads();
    for (int s = 256; s >= 1; s >>= 1) { if (t < s) red[t] += red[t + s]; __syncthreads(); }
    float s1 = red[0]; __syncthreads();
    red[t] = tin; __syncthreads();
    for (int s = 256; s >= 1; s >>= 1) { if (t < s) red[t] += red[t + s]; __syncthreads(); }
    float sin_ = red[0]; __syncthreads();

    if (t == 0) {
        float lori_a = -suma / (float)NN;
        float lori_b = -sumb / (float)NN;
        float global_loss = 0.5f * lori_a + 0.5f * lori_b;
        float loss0 = s0 / (float)GG;
        float loss1 = s1 / (float)GG;
        float inter = 0.5f * (loss0 + loss1);
        float inner = -(sin_ / (float)GG);
        out[0] = global_loss + inter + inner;
    }
}

// ---------------- launcher ----------------
extern "C" void kernel_launch(void* const* d_in, const int* in_sizes, int n_in,
                              void* d_out, int out_size) {
    const float* za  = (const float*)d_in[0];
    const float* zb  = (const float*)d_in[1];
    const float* pos = (const float*)d_in[2];
    const float* W1  = (const float*)d_in[4];
    const float* b1  = (const float*)d_in[5];
    const float* a1  = (const float*)d_in[6];
    const float* g1  = (const float*)d_in[7];
    const float* be1 = (const float*)d_in[8];
    const float* W2  = (const float*)d_in[9];
    const float* b2  = (const float*)d_in[10];
    const float* a2  = (const float*)d_in[11];
    const float* g2  = (const float*)d_in[12];
    const float* be2 = (const float*)d_in[13];
    const float* W3  = (const float*)d_in[14];
    const float* b3  = (const float*)d_in[15];
    float* out = (float*)d_out;

    __nv_bfloat16 *x0h, *x0l, *x1h, *x1l, *x2h, *x2l;
    __nv_bfloat16 *w1h, *w1l, *w2h, *w2l, *w3h, *w3l;
    float* projp;
    cudaGetSymbolAddress((void**)&x0h, g_x0h);
    cudaGetSymbolAddress((void**)&x0l, g_x0l);
    cudaGetSymbolAddress((void**)&x1h, g_x1h);
    cudaGetSymbolAddress((void**)&x1l, g_x1l);
    cudaGetSymbolAddress((void**)&x2h, g_x2h);
    cudaGetSymbolAddress((void**)&x2l, g_x2l);
    cudaGetSymbolAddress((void**)&w1h, g_w1h);
    cudaGetSymbolAddress((void**)&w1l, g_w1l);
    cudaGetSymbolAddress((void**)&w2h, g_w2h);
    cudaGetSymbolAddress((void**)&w2l, g_w2l);
    cudaGetSymbolAddress((void**)&w3h, g_w3h);
    cudaGetSymbolAddress((void**)&w3l, g_w3l);
    cudaGetSymbolAddress((void**)&projp, g_proj);

    cudaFuncSetAttribute(mlp_mma, cudaFuncAttributeMaxDynamicSharedMemorySize,
                         MLP_SMEM_TOTAL);
    cudaFuncSetAttribute(sim_pair, cudaFuncAttributeMaxDynamicSharedMemorySize,
                         SIM_SMEM_TOTAL);

    // fused prep: input split + weight transpose/split + accumulator zeroing
    prep_kernel<<<(NN * HH + 255) / 256, 256>>>(za, zb, W1, W2, W3);

    // MLP (bf16x3 tensor path — projections must stay near-fp32 accurate)
    mlp_mma<<<dim3(4, 128), 256, MLP_SMEM_TOTAL>>>(x0h, x0l, w1h, w1l, HH,
                                                   b1, a1, g1, be1,
                                                   x1h, x1l, nullptr, nullptr, 0);
    mlp_mma<<<dim3(4, 128), 256, MLP_SMEM_TOTAL>>>(x1h, x1l, w2h, w2l, HH,
                                                   b2, a2, g2, be2,
                                                   x2h, x2l, nullptr, nullptr, 0);
    mlp_mma<<<dim3(2, 128), 256, MLP_SMEM_TOTAL>>>(x2h, x2l, w3h, w3l, HH,
                                                   b3, nullptr, nullptr, nullptr,
                                                   nullptr, nullptr, projp, out + 1, 1);

    // normalize + bf16 quantize for sim
    norm_split_kernel<<<NN / 8, 256>>>();

    // paired-tile tensor-core similarity + fused reductions
    sim_pair<<<dim3(GG, GG), 256, SIM_SMEM_TOTAL>>>(pos);

    finalize_kernel<<<1, 512>>>(out);
}

// round 17
// speedup vs baseline: 1.0071x; 1.0071x over previous
#include <cuda_runtime.h>
#include <cuda_bf16.h>
#include <math.h>
#include <stdint.h>

// Problem constants
#define NN    8192
#define HH    512
#define DD    256
#define GG    64
#define M2    16384
#define EPS_G 1e-6f
#define EPS_L 1e-5f

// ---------------- scratch (static device allocations; no cudaMalloc) ----------------
__device__ __nv_bfloat16 g_x0h[M2 * HH], g_x0l[M2 * HH];  // layer1 input (za|zb split)
__device__ __nv_bfloat16 g_x1h[M2 * HH], g_x1l[M2 * HH];  // layer1 out / layer2 in
__device__ __nv_bfloat16 g_x2h[M2 * HH], g_x2l[M2 * HH];  // layer2 out / layer3 in
__device__ __nv_bfloat16 g_w1h[HH * HH], g_w1l[HH * HH];  // W1^T hi/lo  [N,K]
__device__ __nv_bfloat16 g_w2h[HH * HH], g_w2l[HH * HH];  // W2^T
__device__ __nv_bfloat16 g_w3h[DD * HH], g_w3l[DD * HH];  // W3^T  [256,512]
__device__ float g_proj[NN * (2 * DD)];                   // fp32 projections (interleaved)
__device__ __nv_bfloat16 g_Ahi[NN * DD];                  // normalized * 2/tau (bf16)
__device__ __nv_bfloat16 g_Bhi[NN * DD];                  // normalized (bf16)
__device__ float g_rowsum[NN];
__device__ float g_colsum[NN];
__device__ float g_rowdot[NN];
__device__ float g_coldot[NN];
__device__ float g_bsim[GG * GG];
__device__ float g_psg[GG];

// ---------------- portable tensor-core helpers (sm_80+ baseline ISA) ----------------
__device__ __forceinline__ uint32_t smem_u32(const void* p) {
    uint32_t a;
    asm("{ .reg .u64 t; cvta.to.shared.u64 t, %1; cvt.u32.u64 %0, t; }" : "=r"(a) : "l"(p));
    return a;
}
__device__ __forceinline__ void ldm_x4(uint32_t* r, uint32_t a) {
    asm volatile("ldmatrix.sync.aligned.m8n8.x4.shared.b16 {%0,%1,%2,%3}, [%4];"
                 : "=r"(r[0]), "=r"(r[1]), "=r"(r[2]), "=r"(r[3]) : "r"(a));
}
__device__ __forceinline__ void ldm_x2(uint32_t* r, uint32_t a) {
    asm volatile("ldmatrix.sync.aligned.m8n8.x2.shared.b16 {%0,%1}, [%2];"
                 : "=r"(r[0]), "=r"(r[1]) : "r"(a));
}
__device__ __forceinline__ void mma_bf16(float* c, const uint32_t* a, const uint32_t* b) {
    asm volatile("mma.sync.aligned.m16n8k16.row.col.f32.bf16.bf16.f32 "
                 "{%0,%1,%2,%3}, {%4,%5,%6,%7}, {%8,%9}, {%0,%1,%2,%3};"
                 : "+f"(c[0]), "+f"(c[1]), "+f"(c[2]), "+f"(c[3])
                 : "r"(a[0]), "r"(a[1]), "r"(a[2]), "r"(a[3]), "r"(b[0]), "r"(b[1]));
}
__device__ __forceinline__ void split_bf16(float v, __nv_bfloat16& hi, __nv_bfloat16& lo) {
    hi = __float2bfloat16(v);
    lo = __float2bfloat16(v - __bfloat162float(hi));
}
__device__ __forceinline__ void cp_async16(uint32_t saddr, const void* gptr) {
    asm volatile("cp.async.cg.shared.global [%0], [%1], 16;"
                 :: "r"(saddr), "l"(gptr) : "memory");
}
__device__ __forceinline__ void cp_commit() {
    asm volatile("cp.async.commit_group;" ::: "memory");
}
__device__ __forceinline__ void cp_wait0() {
    asm volatile("cp.async.wait_group 0;" ::: "memory");
}
__device__ __forceinline__ void cp_wait1() {
    asm volatile("cp.async.wait_group 1;" ::: "memory");
}

// ---------------- fused prep: input split + weight transpose/split + zeroing --------
__global__ void prep_kernel(const float* __restrict__ za, const float* __restrict__ zb,
                            const float* __restrict__ W1, const float* __restrict__ W2,
                            const float* __restrict__ W3) {
    int t = blockIdx.x * blockDim.x + threadIdx.x;
    if (t < NN * HH) {
        __nv_bfloat16 hi, lo;
        split_bf16(za[t], hi, lo);
        g_x0h[t] = hi; g_x0l[t] = lo;
        split_bf16(zb[t], hi, lo);
        g_x0h[t + NN * HH] = hi; g_x0l[t + NN * HH] = lo;
    }
    if (t < NN) {
        g_rowsum[t] = 0.f; g_colsum[t] = 0.f;
        g_rowdot[t] = 0.f; g_coldot[t] = 0.f;
    }
    if (t < 2 * HH * HH + DD * HH) {
        const float* W; __nv_bfloat16 *Th, *Tl; int Nw, e;
        if (t < HH * HH)            { W = W1; Th = g_w1h; Tl = g_w1l; Nw = HH; e = t; }
        else if (t < 2 * HH * HH)   { W = W2; Th = g_w2h; Tl = g_w2l; Nw = HH; e = t - HH * HH; }
        else                        { W = W3; Th = g_w3h; Tl = g_w3l; Nw = DD; e = t - 2 * HH * HH; }
        int n = e >> 9, k = e & 511;
        float v = W[(size_t)k * Nw + n];
        __nv_bfloat16 hi, lo; split_bf16(v, hi, lo);
        Th[e] = hi; Tl[e] = lo;
    }
}

// ---------------- bf16x3 MLP GEMM (R14-proven mainloop: per-mi A fragments) ----------
#define SM_A_HI 0
#define SM_A_LO 16384
#define SM_B_HI 32768
#define SM_B_LO 49152
#define MLP_SMEM_TOTAL 65536

__global__ __launch_bounds__(256, 2) void mlp_mma(
    const __nv_bfloat16* __restrict__ Ah, const __nv_bfloat16* __restrict__ Al,
    const __nv_bfloat16* __restrict__ Bh, const __nv_bfloat16* __restrict__ Bl,
    int K,
    const float* __restrict__ bias,
    const float* __restrict__ aP, const float* __restrict__ gP, const float* __restrict__ beP,
    __nv_bfloat16* __restrict__ Oh, __nv_bfloat16* __restrict__ Ol,
    float* __restrict__ Cp, float* __restrict__ C2,
    int mode)
{
    extern __shared__ char smem[];
    uint32_t sb = smem_u32(smem);
    int tid = threadIdx.x;
    int w = tid >> 5, lane = tid & 31;
    int wm = w >> 2, wn = w & 3;          // 2x4 warp grid, 64x32 warp tile
    int i0 = blockIdx.y * 128, j0 = blockIdx.x * 128;

    float c[4][4][4];
#pragma unroll
    for (int mi = 0; mi < 4; mi++)
#pragma unroll
        for (int ni = 0; ni < 4; ni++)
#pragma unroll
            for (int q = 0; q < 4; q++) c[mi][ni][q] = 0.f;

    int srow = tid >> 1, sseg = tid & 1;
    size_t aidx0 = (size_t)(i0 + srow) * K + sseg * 32;
    size_t bidx0 = (size_t)(j0 + srow) * K + sseg * 32;

    int rA = lane & 15;
    int cbA = (lane >> 4) * 16;
    int rB = lane & 7;
    int cbB = ((lane >> 3) & 1) * 16;

    int nkc = K >> 6;
    for (int kc = 0; kc < nkc; kc++) {
        size_t aidx = aidx0 + kc * 64;
        size_t bidx = bidx0 + kc * 64;
#pragma unroll
        for (int q = 0; q < 4; q++) {
            uint32_t off = (uint32_t)(srow * 128 + sseg * 64 + q * 16);
            uint32_t sw = off ^ ((off >> 3) & 0x70);
            *(uint4*)(smem + SM_A_HI + sw) = *(const uint4*)(Ah + aidx + q * 8);
            *(uint4*)(smem + SM_A_LO + sw) = *(const uint4*)(Al + aidx + q * 8);
            *(uint4*)(smem + SM_B_HI + sw) = *(const uint4*)(Bh + bidx + q * 8);
            *(uint4*)(smem + SM_B_LO + sw) = *(const uint4*)(Bl + bidx + q * 8);
        }
        __syncthreads();

#pragma unroll
        for (int ks = 0; ks < 4; ks++) {
            uint32_t bhi[4][2], blo[4][2];
#pragma unroll
            for (int ni = 0; ni < 4; ni++) {
                uint32_t off = (uint32_t)((wn * 32 + ni * 8 + rB) * 128 + ks * 32 + cbB);
                uint32_t sw = off ^ ((off >> 3) & 0x70);
                ldm_x2(bhi[ni], sb + SM_B_HI + sw);
                ldm_x2(blo[ni], sb + SM_B_LO + sw);
            }
#pragma unroll
            for (int mi = 0; mi < 4; mi++) {
                uint32_t ahi[4], alo[4];
                uint32_t off = (uint32_t)((wm * 64 + mi * 16 + rA) * 128 + ks * 32 + cbA);
                uint32_t sw = off ^ ((off >> 3) & 0x70);
                ldm_x4(ahi, sb + SM_A_HI + sw);
                ldm_x4(alo, sb + SM_A_LO + sw);
#pragma unroll
                for (int ni = 0; ni < 4; ni++) {
                    mma_bf16(c[mi][ni], ahi, bhi[ni]);
                    mma_bf16(c[mi][ni], ahi, blo[ni]);
                    mma_bf16(c[mi][ni], alo, bhi[ni]);
                }
            }
        }
        __syncthreads();
    }

    // ---- epilogue ----
    if (mode == 0) {
        float a0 = aP[0];
#pragma unroll
        for (int mi = 0; mi < 4; mi++) {
#pragma unroll
            for (int h = 0; h < 2; h++) {
                int m = i0 + wm * 64 + mi * 16 + h * 8 + (lane >> 2);
#pragma unroll
                for (int ni = 0; ni < 4; ni++) {
                    int c0 = j0 + wn * 32 + ni * 8 + (lane & 3) * 2;
                    float v0 = tanhf(a0 * (c[mi][ni][2 * h + 0] + bias[c0])) * gP[c0] + beP[c0];
                    float v1 = tanhf(a0 * (c[mi][ni][2 * h + 1] + bias[c0 + 1])) * gP[c0 + 1] + beP[c0 + 1];
                    __nv_bfloat16 h0, l0, h1, l1;
                    split_bf16(v0, h0, l0);
                    split_bf16(v1, h1, l1);
                    size_t idx = (size_t)m * 512 + c0;
                    *(__nv_bfloat162*)(Oh + idx) = __nv_bfloat162(h0, h1);
                    *(__nv_bfloat162*)(Ol + idx) = __nv_bfloat162(l0, l1);
                }
            }
        }
    } else {
#pragma unroll
        for (int mi = 0; mi < 4; mi++) {
#pragma unroll
            for (int h = 0; h < 2; h++) {
                int m = i0 + wm * 64 + mi * 16 + h * 8 + (lane >> 2);
                size_t base = (m < NN) ? ((size_t)m * 512) : ((size_t)(m - NN) * 512 + 256);
#pragma unroll
                for (int ni = 0; ni < 4; ni++) {
                    int c0 = j0 + wn * 32 + ni * 8 + (lane & 3) * 2;
                    float v0 = c[mi][ni][2 * h + 0] + bias[c0];
                    float v1 = c[mi][ni][2 * h + 1] + bias[c0 + 1];
                    v0 = v0 / (1.f + expf(-v0));
                    v1 = v1 / (1.f + expf(-v1));
                    size_t pr = base + c0;
                    Cp[pr] = v0; Cp[pr + 1] = v1;
                    C2[pr] = v0; C2[pr + 1] = v1;
                }
            }
        }
    }
}

// ---------------- per-row norm + bf16 quantize (2/tau folded into A) ----------------
__global__ void norm_split_kernel() {
    int warp = (blockIdx.x * blockDim.x + threadIdx.x) >> 5;
    int lane = threadIdx.x & 31;
    if (warp >= NN) return;
    const float* pa = g_proj + (size_t)warp * 512;
    float sa = 0.f, sb = 0.f;
#pragma unroll
    for (int k = lane; k < 256; k += 32) {
        float v = pa[k];        sa += v * v;
        float w = pa[256 + k];  sb += w * w;
    }
#pragma unroll
    for (int o = 16; o; o >>= 1) {
        sa += __shfl_xor_sync(0xffffffffu, sa, o);
        sb += __shfl_xor_sync(0xffffffffu, sb, o);
    }
    float ia = 2.0f * rsqrtf(sa);
    float ib = rsqrtf(sb);
#pragma unroll
    for (int k = lane; k < 256; k += 32) {
        g_Ahi[(size_t)warp * 256 + k] = __float2bfloat16(pa[k] * ia);
        g_Bhi[(size_t)warp * 256 + k] = __float2bfloat16(pa[256 + k] * ib);
    }
}

// ---------------- paired-tile 1-term bf16 sim + fused reductions ---------------------
#define SIMD_A0 0
#define SIMD_B0 16384
#define SIMD_A1 32768
#define SIMD_B1 49152
#define SM_RS   66048
#define SM_RD   66560
#define SM_CS   67072
#define SM_CD   67584
#define SM_TS   68096
#define SM_PSG  68100
#define SIM_SMEM_TOTAL 68352

__global__ __launch_bounds__(256, 2) void sim_pair(const float* __restrict__ pos) {
    int by = blockIdx.y, bx = blockIdx.x;
    if (by > bx) return;                  // upper-triangle CTAs only
    extern __shared__ char smem[];
    uint32_t sb = smem_u32(smem);
    int tid = threadIdx.x;
    int w = tid >> 5, lane = tid & 31;
    int wm = w >> 2, wn = w & 3;

    float* s_rs = (float*)(smem + SM_RS);
    float* s_rd = (float*)(smem + SM_RD);
    float* s_cs = (float*)(smem + SM_CS);
    float* s_cd = (float*)(smem + SM_CD);
    float* smf  = (float*)smem;

    int srow = tid >> 1, sseg = tid & 1;
    int rA = lane & 15;
    int cbA = (lane >> 4) * 16;
    int rB = lane & 7;
    int cbB = ((lane >> 3) & 1) * 16;
    uint32_t soff0 = (uint32_t)(srow * 128 + sseg * 64);

    int npass = (by == bx) ? 1 : 2;
    for (int pass = 0; pass < npass; pass++) {
        int I = pass ? bx : by;
        int J = pass ? by : bx;
        int i0 = I * 128, j0 = J * 128;

        if (tid == 0) { *(float*)(smem + SM_TS) = 0.f; *(float*)(smem + SM_PSG) = 0.f; }
        if (tid < 128) { s_rs[tid] = 0.f; s_rd[tid] = 0.f; }

        float c[4][4][4];
#pragma unroll
        for (int mi = 0; mi < 4; mi++)
#pragma unroll
            for (int ni = 0; ni < 4; ni++)
#pragma unroll
                for (int q = 0; q < 4; q++) c[mi][ni][q] = 0.f;

        size_t aidx0 = (size_t)(i0 + srow) * 256 + sseg * 32;
        size_t bidx0 = (size_t)(j0 + srow) * 256 + sseg * 32;

        // prologue: stage chunk 0 into buf0
#pragma unroll
        for (int q = 0; q < 4; q++) {
            uint32_t off = soff0 + q * 16;
            uint32_t sw = off ^ ((off >> 3) & 0x70);
            cp_async16(sb + SIMD_A0 + sw, g_Ahi + aidx0 + q * 8);
            cp_async16(sb + SIMD_B0 + sw, g_Bhi + bidx0 + q * 8);
        }
        cp_commit();

        for (int kc = 0; kc < 4; kc++) {
            if (kc < 3) {
                uint32_t abase = (kc & 1) ? SIMD_A0 : SIMD_A1;   // next buffer
                uint32_t bbase = (kc & 1) ? SIMD_B0 : SIMD_B1;
                size_t aidx = aidx0 + (kc + 1) * 64;
                size_t bidx = bidx0 + (kc + 1) * 64;
#pragma unroll
                for (int q = 0; q < 4; q++) {
                    uint32_t off = soff0 + q * 16;
                    uint32_t sw = off ^ ((off >> 3) & 0x70);
                    cp_async16(sb + abase + sw, g_Ahi + aidx + q * 8);
                    cp_async16(sb + bbase + sw, g_Bhi + bidx + q * 8);
                }
                cp_commit();
                cp_wait1();
            } else {
                cp_wait0();
            }
            __syncthreads();

            uint32_t aC = (kc & 1) ? SIMD_A1 : SIMD_A0;          // current buffer
            uint32_t bC = (kc & 1) ? SIMD_B1 : SIMD_B0;
#pragma unroll
            for (int ks = 0; ks < 4; ks++) {
                uint32_t bf[4][2];
#pragma unroll
                for (int ni = 0; ni < 4; ni++) {
                    uint32_t off = (uint32_t)((wn * 32 + ni * 8 + rB) * 128 + ks * 32 + cbB);
                    uint32_t sw = off ^ ((off >> 3) & 0x70);
                    ldm_x2(bf[ni], sb + bC + sw);
                }
#pragma unroll
                for (int mi = 0; mi < 4; mi++) {
                    uint32_t af[4];
                    uint32_t off = (uint32_t)((wm * 64 + mi * 16 + rA) * 128 + ks * 32 + cbA);
                    uint32_t sw = off ^ ((off >> 3) & 0x70);
                    ldm_x4(af, sb + aC + sw);
#pragma unroll
                    for (int ni = 0; ni < 4; ni++)
                        mma_bf16(c[mi][ni], af, bf[ni]);
                }
            }
            __syncthreads();
        }

        // ---- epilogue: exp, row reductions + pos row-pass, stage m-tile ----
        float tsl = 0.f;
#pragma unroll
        for (int mi = 0; mi < 4; mi++) {
#pragma unroll
            for (int h = 0; h < 2; h++) {
                int row_local = wm * 64 + mi * 16 + h * 8 + (lane >> 2);
                int gi = i0 + row_local;
                float rsum = 0.f, rdot = 0.f;
#pragma unroll
                for (int ni = 0; ni < 4; ni++) {
                    int col_local = wn * 32 + ni * 8 + (lane & 3) * 2;
                    float e0 = expf(c[mi][ni][2 * h + 0]);
                    float e1 = expf(c[mi][ni][2 * h + 1]);
                    smf[(size_t)row_local * 129 + col_local]     = e0;
                    smf[(size_t)row_local * 129 + col_local + 1] = e1;
                    const float2 p = *(const float2*)(pos + (size_t)gi * NN + j0 + col_local);
                    rsum += e0 + e1;
                    rdot += e0 * p.x + e1 * p.y;
                }
                atomicAdd(&s_rs[row_local], rsum);
                atomicAdd(&s_rd[row_local], rdot);
                tsl += rsum;
            }
        }
#pragma unroll
        for (int o = 16; o; o >>= 1) tsl += __shfl_xor_sync(0xffffffffu, tsl, o);
        if (lane == 0) atomicAdd((float*)(smem + SM_TS), tsl);
        __syncthreads();   // m-tile complete

        // column reductions: warp w owns pos-rows [w*16, w*16+16); per row the
        // 32 lanes read one contiguous float4 each (coalesced 512B), then
        // shuffle-reduce; lane 0 direct-stores (unique writer per cc).
        {
            int cc0 = w * 16;
            for (int r = 0; r < 16; r++) {
                int cc = cc0 + r;
                const float4 p = *(const float4*)(pos + (size_t)(j0 + cc) * NN + i0 + lane * 4);
                float m0 = smf[(size_t)(lane * 4 + 0) * 129 + cc];
                float m1 = smf[(size_t)(lane * 4 + 1) * 129 + cc];
                float m2 = smf[(size_t)(lane * 4 + 2) * 129 + cc];
                float m3 = smf[(size_t)(lane * 4 + 3) * 129 + cc];
                float cs = m0 + m1 + m2 + m3;
                float cd = m0 * p.x + m1 * p.y + m2 * p.z + m3 * p.w;
#pragma unroll
                for (int o = 16; o; o >>= 1) {
                    cs += __shfl_xor_sync(0xffffffffu, cs, o);
                    cd += __shfl_xor_sync(0xffffffffu, cd, o);
                }
                if (lane == 0) { s_cs[cc] = cs; s_cd[cc] = cd; }
            }
        }
        if (i0 == j0 && tid < 128)
            atomicAdd((float*)(smem + SM_PSG), smf[(size_t)tid * 129 + tid]);
        __syncthreads();

        if (tid < 128) {
            atomicAdd(&g_rowsum[i0 + tid], s_rs[tid]);
            atomicAdd(&g_rowdot[i0 + tid], s_rd[tid]);
            atomicAdd(&g_colsum[j0 + tid], s_cs[tid]);
            atomicAdd(&g_coldot[j0 + tid], s_cd[tid]);
        }
        if (tid == 0) {
            g_bsim[I * GG + J] = *(float*)(smem + SM_TS);   // unique (I,J) per pass
            if (I == J) g_psg[I] = *(float*)(smem + SM_PSG);
        }
        __syncthreads();   // protect smem before next pass restages
    }
}

// ---------------- final scalar loss ----------------
__global__ void finalize_kernel(float* __restrict__ out) {
    __shared__ float red[512];
    int t = threadIdx.x;

    float la = 0.f, lb = 0.f;
    for (int i = t; i < NN; i += 512) {
        la += logf(g_rowdot[i] / (g_rowsum[i] + EPS_G));
        lb += logf(g_coldot[i] / (g_colsum[i] + EPS_G));
    }
    red[t] = la; __syncthreads();
    for (int s = 256; s >= 1; s >>= 1) { if (t < s) red[t] += red[t + s]; __syncthreads(); }
    float suma = red[0]; __syncthreads();
    red[t] = lb; __syncthreads();
    for (int s = 256; s >= 1; s >>= 1) { if (t < s) red[t] += red[t + s]; __syncthreads(); }
    float sumb = red[0]; __syncthreads();

    float t0 = 0.f, t1 = 0.f, tin = 0.f;
    if (t < GG) {
        float graph = g_bsim[t * GG + t];
        float n0 = 0.f, n1 = 0.f;
        for (int a = 0; a < GG; a++) { n0 += g_bsim[a * GG + t]; n1 += g_bsim[t * GG + a]; }
        n0 -= graph; n1 -= graph;
        float psg = g_psg[t];
        t0  = logf(psg / (n0 + EPS_L));
        t1  = logf(psg / (n1 + EPS_L));
        tin = logf(psg / (graph - psg + EPS_L));
    }
    red[t] = t0; __syncthreads();
    for (int s = 256; s >= 1; s >>= 1) { if (t < s) red[t] += red[t + s]; __syncthreads(); }
    float s0 = red[0]; __syncthreads();
    red[t] = t1; __syncthreads();
    for (int s = 256; s >= 1; s >>= 1) { if (t < s) red[t] += red[t + s]; __syncthreads(); }
    float s1 = red[0]; __syncthreads();
    red[t] = tin; __syncthreads();
    for (int s = 256; s >= 1; s >>= 1) { if (t < s) red[t] += red[t + s]; __syncthreads(); }
    float sin_ = red[0]; __syncthreads();

    if (t == 0) {
        float lori_a = -suma / (float)NN;
        float lori_b = -sumb / (float)NN;
        float global_loss = 0.5f * lori_a + 0.5f * lori_b;
        float loss0 = s0 / (float)GG;
        float loss1 = s1 / (float)GG;
        float inter = 0.5f * (loss0 + loss1);
        float inner = -(sin_ / (float)GG);
        out[0] = global_loss + inter + inner;
    }
}

// ---------------- launcher ----------------
extern "C" void kernel_launch(void* const* d_in, const int* in_sizes, int n_in,
                              void* d_out, int out_size) {
    const float* za  = (const float*)d_in[0];
    const float* zb  = (const float*)d_in[1];
    const float* pos = (const float*)d_in[2];
    const float* W1  = (const float*)d_in[4];
    const float* b1  = (const float*)d_in[5];
    const float* a1  = (const float*)d_in[6];
    const float* g1  = (const float*)d_in[7];
    const float* be1 = (const float*)d_in[8];
    const float* W2  = (const float*)d_in[9];
    const float* b2  = (const float*)d_in[10];
    const float* a2  = (const float*)d_in[11];
    const float* g2  = (const float*)d_in[12];
    const float* be2 = (const float*)d_in[13];
    const float* W3  = (const float*)d_in[14];
    const float* b3  = (const float*)d_in[15];
    float* out = (float*)d_out;

    __nv_bfloat16 *x0h, *x0l, *x1h, *x1l, *x2h, *x2l;
    __nv_bfloat16 *w1h, *w1l, *w2h, *w2l, *w3h, *w3l;
    float* projp;
    cudaGetSymbolAddress((void**)&x0h, g_x0h);
    cudaGetSymbolAddress((void**)&x0l, g_x0l);
    cudaGetSymbolAddress((void**)&x1h, g_x1h);
    cudaGetSymbolAddress((void**)&x1l, g_x1l);
    cudaGetSymbolAddress((void**)&x2h, g_x2h);
    cudaGetSymbolAddress((void**)&x2l, g_x2l);
    cudaGetSymbolAddress((void**)&w1h, g_w1h);
    cudaGetSymbolAddress((void**)&w1l, g_w1l);
    cudaGetSymbolAddress((void**)&w2h, g_w2h);
    cudaGetSymbolAddress((void**)&w2l, g_w2l);
    cudaGetSymbolAddress((void**)&w3h, g_w3h);
    cudaGetSymbolAddress((void**)&w3l, g_w3l);
    cudaGetSymbolAddress((void**)&projp, g_proj);

    cudaFuncSetAttribute(mlp_mma, cudaFuncAttributeMaxDynamicSharedMemorySize,
                         MLP_SMEM_TOTAL);
    cudaFuncSetAttribute(sim_pair, cudaFuncAttributeMaxDynamicSharedMemorySize,
                         SIM_SMEM_TOTAL);

    // fused prep: input split + weight transpose/split + accumulator zeroing
    prep_kernel<<<(NN * HH + 255) / 256, 256>>>(za, zb, W1, W2, W3);

    // MLP (bf16x3 tensor path — projections must stay near-fp32 accurate)
    mlp_mma<<<dim3(4, 128), 256, MLP_SMEM_TOTAL>>>(x0h, x0l, w1h, w1l, HH,
                                                   b1, a1, g1, be1,
                                                   x1h, x1l, nullptr, nullptr, 0);
    mlp_mma<<<dim3(4, 128), 256, MLP_SMEM_TOTAL>>>(x1h, x1l, w2h, w2l, HH,
                                                   b2, a2, g2, be2,
                                                   x2h, x2l, nullptr, nullptr, 0);
    mlp_mma<<<dim3(2, 128), 256, MLP_SMEM_TOTAL>>>(x2h, x2l, w3h, w3l, HH,
                                                   b3, nullptr, nullptr, nullptr,
                                                   nullptr, nullptr, projp, out + 1, 1);

    // normalize + bf16 quantize for sim
    norm_split_kernel<<<NN / 8, 256>>>();

    // paired-tile tensor-core similarity + fused reductions
    sim_pair<<<dim3(GG, GG), 256, SIM_SMEM_TOTAL>>>(pos);

    finalize_kernel<<<1, 512>>>(out);
}